// round 14
// baseline (speedup 1.0000x reference)
#include <cuda_runtime.h>
#include <cuda_bf16.h>
#include <math.h>
#include <stdint.h>

// Problem constants
constexpr int TT  = 4096;   // sequence length
constexpr int CC  = 2048;   // model dim
constexpr int NH  = 16;     // query heads
constexpr int NKV = 4;      // kv heads
constexpr int HD  = 128;    // head dim

// Scratch (device globals; no allocation allowed)
__device__ float g_q[(size_t)TT * CC];
__device__ float g_k[(size_t)TT * NKV * HD];
__device__ float g_v[(size_t)TT * NKV * HD];
__device__ __nv_bfloat16 g_atthi[(size_t)TT * CC];
__device__ __nv_bfloat16 g_attlo[(size_t)TT * CC];
__device__ __nv_bfloat16 g_xhi[(size_t)TT * CC];
__device__ __nv_bfloat16 g_xlo[(size_t)TT * CC];
// weights pair-packed: [K/2][N] uint32, each uint32 = (bf16 k=2kp, bf16 k=2kp+1)
__device__ uint32_t g_wqhi[(size_t)(CC / 2) * CC];
__device__ uint32_t g_wqlo[(size_t)(CC / 2) * CC];
__device__ uint32_t g_wkhi[(size_t)(CC / 2) * NKV * HD];
__device__ uint32_t g_wklo[(size_t)(CC / 2) * NKV * HD];
__device__ uint32_t g_wvhi[(size_t)(CC / 2) * NKV * HD];
__device__ uint32_t g_wvlo[(size_t)(CC / 2) * NKV * HD];
__device__ uint32_t g_wohi[(size_t)(CC / 2) * CC];
__device__ uint32_t g_wolo[(size_t)(CC / 2) * CC];
__device__ float g_cos[(size_t)TT * HD];
__device__ float g_sin[(size_t)TT * HD];

// ---------- helpers ----------
__device__ __forceinline__ unsigned f2tf(float x) {
    unsigned u; asm("cvt.rna.tf32.f32 %0, %1;" : "=r"(u) : "f"(x)); return u;
}
__device__ __forceinline__ float tf2f(unsigned u) { return __uint_as_float(u); }

__device__ __forceinline__ void mma_tf32(float c[4], const unsigned a[4], const unsigned b[2]) {
    asm volatile(
        "mma.sync.aligned.m16n8k8.row.col.f32.tf32.tf32.f32 "
        "{%0,%1,%2,%3}, {%4,%5,%6,%7}, {%8,%9}, {%0,%1,%2,%3};\n"
        : "+f"(c[0]), "+f"(c[1]), "+f"(c[2]), "+f"(c[3])
        : "r"(a[0]), "r"(a[1]), "r"(a[2]), "r"(a[3]), "r"(b[0]), "r"(b[1]));
}

__device__ __forceinline__ void mma_bf16(float c[4], const unsigned a[4], const unsigned b[2]) {
    asm volatile(
        "mma.sync.aligned.m16n8k16.row.col.f32.bf16.bf16.f32 "
        "{%0,%1,%2,%3}, {%4,%5,%6,%7}, {%8,%9}, {%0,%1,%2,%3};\n"
        : "+f"(c[0]), "+f"(c[1]), "+f"(c[2]), "+f"(c[3])
        : "r"(a[0]), "r"(a[1]), "r"(a[2]), "r"(a[3]), "r"(b[0]), "r"(b[1]));
}

__device__ __forceinline__ uint32_t cvta_smem(const void* p) {
    uint32_t a;
    asm("{ .reg .u64 t; cvta.to.shared.u64 t, %1; cvt.u32.u64 %0, t; }" : "=r"(a) : "l"(p));
    return a;
}
__device__ __forceinline__ void cpa16(uint32_t dst, const void* src) {
    asm volatile("cp.async.cg.shared.global [%0], [%1], 16;" :: "r"(dst), "l"(src) : "memory");
}
__device__ __forceinline__ void cpa_commit() {
    asm volatile("cp.async.commit_group;" ::: "memory");
}
template<int N> __device__ __forceinline__ void cpa_wait() {
    asm volatile("cp.async.wait_group %0;" :: "n"(N) : "memory");
}

__device__ __forceinline__ void bsplit(float v, __nv_bfloat16 &h, __nv_bfloat16 &l) {
    h = __float2bfloat16_rn(v);
    l = __float2bfloat16_rn(v - __bfloat162float(h));
}

// ---------- RoPE tables (fp64-accurate) ----------
__global__ void rope_table_kernel(float* __restrict__ ctab, float* __restrict__ stab) {
    int t = blockIdx.x;
    int d = threadIdx.x;            // 0..127
    int fi = d & 63;
    double inv = exp(-(double)fi * (log(10000.0) / 64.0));
    double ang = (double)t * inv;
    ctab[(size_t)t * HD + d] = (float)cos(ang);
    stab[(size_t)t * HD + d] = (float)sin(ang);
}

// ---------- A-side split: fp32 row-major -> bf16 hi/lo row-major ----------
__global__ __launch_bounds__(256) void split_a(
    const float* __restrict__ in, __nv_bfloat16* __restrict__ hi, __nv_bfloat16* __restrict__ lo)
{
    size_t i = (size_t)blockIdx.x * 256 + threadIdx.x;      // over elems/4
    float4 v = reinterpret_cast<const float4*>(in)[i];
    __nv_bfloat16 h0, h1, h2, h3, l0, l1, l2, l3;
    bsplit(v.x, h0, l0); bsplit(v.y, h1, l1); bsplit(v.z, h2, l2); bsplit(v.w, h3, l3);
    __nv_bfloat162 ph0; ph0.x = h0; ph0.y = h1;
    __nv_bfloat162 ph1; ph1.x = h2; ph1.y = h3;
    __nv_bfloat162 pl0; pl0.x = l0; pl0.y = l1;
    __nv_bfloat162 pl1; pl1.x = l2; pl1.y = l3;
    reinterpret_cast<__nv_bfloat162*>(hi)[2 * i]     = ph0;
    reinterpret_cast<__nv_bfloat162*>(hi)[2 * i + 1] = ph1;
    reinterpret_cast<__nv_bfloat162*>(lo)[2 * i]     = pl0;
    reinterpret_cast<__nv_bfloat162*>(lo)[2 * i + 1] = pl1;
}

// ---------- B-side split + k-pair pack: fp32 [K][N] -> uint32 [K/2][N] ----------
__global__ __launch_bounds__(256) void split_b(
    const float* __restrict__ B, uint32_t* __restrict__ hi, uint32_t* __restrict__ lo, int N)
{
    int n  = blockIdx.x * 256 + threadIdx.x;
    int kp = blockIdx.y;
    float v0 = B[(size_t)(2 * kp) * N + n];
    float v1 = B[(size_t)(2 * kp + 1) * N + n];
    __nv_bfloat16 h0, h1, l0, l1;
    bsplit(v0, h0, l0);
    bsplit(v1, h1, l1);
    __nv_bfloat162 ph; ph.x = h0; ph.y = h1;
    __nv_bfloat162 pl; pl.x = l0; pl.y = l1;
    hi[(size_t)kp * N + n] = *reinterpret_cast<uint32_t*>(&ph);
    lo[(size_t)kp * N + n] = *reinterpret_cast<uint32_t*>(&pl);
}

// ---------- split-bf16 GEMM (3-term, pair-packed, cp.async double-buffered) ----------
// C[M,N] = A[M,K] @ B[K,N]; A as hi/lo bf16 row-major (uint32 pairs along K),
// B as hi/lo pair-packed [K/2][N] uint32. 128x128 tile, BK=32 (16 pairs),
// 256 threads (8 warps as 4m x 2n), warp tile 32x64, m16n8k16 bf16 mma.
constexpr int BKP   = 16;                 // k-pairs per tile (= 32 k)
constexpr int A_LD  = 20;                 // uint32 lead (16 used + 4 pad)
constexpr int B_LD  = 136;                // uint32 lead (128 used + 8 pad)
constexpr int SZ_A  = 128 * A_LD;         // 2560 uint32 per A buffer
constexpr int SZ_B  = BKP * B_LD;         // 2176 uint32 per B buffer
constexpr int STGU  = 2 * SZ_A + 2 * SZ_B;   // 9472 uint32 per stage
constexpr int GEMM_SMEM = 2 * STGU * 4;      // 75776 bytes

__global__ __launch_bounds__(256, 2) void gemm_bf16s(
    const uint32_t* __restrict__ Ahi, const uint32_t* __restrict__ Alo,
    const uint32_t* __restrict__ Bh0, const uint32_t* __restrict__ Bl0,
    const uint32_t* __restrict__ Bh1, const uint32_t* __restrict__ Bl1,
    float* __restrict__ C0, float* __restrict__ C1,
    int Kdim, int n0tiles, int Nc0, int Nc1)
{
    extern __shared__ uint32_t smu[];
    const uint32_t sb = cvta_smem(smu);
    const int tid  = threadIdx.x;
    const int lane = tid & 31;
    const int wid  = tid >> 5;
    const int g    = lane >> 2;     // 0..7
    const int tg   = lane & 3;      // 0..3
    const int wm   = (wid & 3) << 5;    // 0,32,64,96
    const int wn   = (wid >> 2) << 6;   // 0,64
    const int bm   = blockIdx.y << 7;
    const int KP   = Kdim >> 1;

    const uint32_t *Bhi, *Blo; float* C; int Nc, bn;
    if ((int)blockIdx.x < n0tiles) { Bhi = Bh0; Blo = Bl0; C = C0; Nc = Nc0; bn = blockIdx.x << 7; }
    else                           { Bhi = Bh1; Blo = Bl1; C = C1; Nc = Nc1; bn = (blockIdx.x - n0tiles) << 7; }

    // copy coordinates
    const int arow = tid >> 1;            // 0..127
    const int acnk = (tid & 1) << 1;      // chunk base 0 or 2 (chunks of 4 uint32)
    const int brow = tid >> 4;            // 0..15
    const int bcnk = tid & 15;            // 0..15 (+16)

    const uint32_t* Asrc_h = Ahi + (size_t)(bm + arow) * KP + (acnk << 2);
    const uint32_t* Asrc_l = Alo + (size_t)(bm + arow) * KP + (acnk << 2);
    const uint32_t* Bsrc_h = Bhi + (size_t)brow * Nc + bn + (bcnk << 2);
    const uint32_t* Bsrc_l = Blo + (size_t)brow * Nc + bn + (bcnk << 2);

    auto load_stage = [&](int s, int kp0) {
        const uint32_t st = sb + (uint32_t)(s * STGU) * 4;
        #pragma unroll
        for (int i = 0; i < 2; i++) {
            uint32_t d = st + (uint32_t)(arow * A_LD + ((acnk + i) << 2)) * 4;
            cpa16(d, Asrc_h + kp0 + (i << 2));
            cpa16(d + SZ_A * 4, Asrc_l + kp0 + (i << 2));
        }
        #pragma unroll
        for (int i = 0; i < 2; i++) {
            int c = bcnk + (i << 4);
            uint32_t d = st + (uint32_t)(2 * SZ_A + brow * B_LD + (c << 2)) * 4;
            cpa16(d, Bsrc_h + (size_t)kp0 * Nc + (i << 6));
            cpa16(d + SZ_B * 4, Bsrc_l + (size_t)kp0 * Nc + (i << 6));
        }
        cpa_commit();
    };

    float acc[2][8][4];
    #pragma unroll
    for (int i = 0; i < 2; i++)
        #pragma unroll
        for (int j = 0; j < 8; j++)
            #pragma unroll
            for (int q = 0; q < 4; q++) acc[i][j][q] = 0.f;

    const int nkt = Kdim >> 5;
    load_stage(0, 0);

    for (int kt = 0; kt < nkt; kt++) {
        if (kt + 1 < nkt) { load_stage((kt + 1) & 1, (kt + 1) * BKP); cpa_wait<1>(); }
        else             { cpa_wait<0>(); }
        __syncthreads();

        const uint32_t* buf = smu + (kt & 1) * STGU;
        const uint32_t* Ah = buf;
        const uint32_t* Al = buf + SZ_A;
        const uint32_t* Bh = buf + 2 * SZ_A;
        const uint32_t* Bl = buf + 2 * SZ_A + SZ_B;

        #pragma unroll
        for (int ks = 0; ks < 2; ks++) {
            const int kpq = (ks << 3) + tg;
            unsigned ahi[2][4], alo[2][4];
            #pragma unroll
            for (int mt = 0; mt < 2; mt++) {
                const int mr = wm + (mt << 4) + g;
                ahi[mt][0] = Ah[mr * A_LD + kpq];
                ahi[mt][1] = Ah[(mr + 8) * A_LD + kpq];
                ahi[mt][2] = Ah[mr * A_LD + kpq + 4];
                ahi[mt][3] = Ah[(mr + 8) * A_LD + kpq + 4];
                alo[mt][0] = Al[mr * A_LD + kpq];
                alo[mt][1] = Al[(mr + 8) * A_LD + kpq];
                alo[mt][2] = Al[mr * A_LD + kpq + 4];
                alo[mt][3] = Al[(mr + 8) * A_LD + kpq + 4];
            }
            #pragma unroll
            for (int nt = 0; nt < 8; nt++) {
                const int nc = wn + (nt << 3) + g;
                unsigned bh[2], bl[2];
                bh[0] = Bh[kpq * B_LD + nc];
                bh[1] = Bh[(kpq + 4) * B_LD + nc];
                bl[0] = Bl[kpq * B_LD + nc];
                bl[1] = Bl[(kpq + 4) * B_LD + nc];
                #pragma unroll
                for (int mt = 0; mt < 2; mt++) {
                    mma_bf16(acc[mt][nt], ahi[mt], bh);
                    mma_bf16(acc[mt][nt], alo[mt], bh);
                    mma_bf16(acc[mt][nt], ahi[mt], bl);
                }
            }
        }
        __syncthreads();
    }

    #pragma unroll
    for (int mt = 0; mt < 2; mt++) {
        #pragma unroll
        for (int nt = 0; nt < 8; nt++) {
            const int row0 = bm + wm + (mt << 4) + g;
            const int col  = bn + wn + (nt << 3) + (tg << 1);
            *reinterpret_cast<float2*>(C + (size_t)row0 * Nc + col) =
                make_float2(acc[mt][nt][0], acc[mt][nt][1]);
            *reinterpret_cast<float2*>(C + (size_t)(row0 + 8) * Nc + col) =
                make_float2(acc[mt][nt][2], acc[mt][nt][3]);
        }
    }
}

// ---------- fused RMSnorm + RoPE (per (t, head) row of 128) ----------
__global__ __launch_bounds__(128) void rmsnorm_rope(
    float* __restrict__ p, const float* __restrict__ ctab, const float* __restrict__ stab, int nh)
{
    const int t = blockIdx.x;
    const int h = blockIdx.y;
    const int d = threadIdx.x;      // 0..127
    const int stride = nh * HD;
    float* row = p + (size_t)t * stride + h * HD;

    float v = row[d];
    float s = v * v;
    #pragma unroll
    for (int o = 16; o > 0; o >>= 1) s += __shfl_xor_sync(0xffffffffu, s, o);
    __shared__ float ws[4];
    __shared__ float xs[128];
    if ((d & 31) == 0) ws[d >> 5] = s;
    __syncthreads();
    float tot = ws[0] + ws[1] + ws[2] + ws[3];
    float r = rsqrtf(tot * (1.0f / 128.0f) + 1e-6f);
    float xn = v * r;
    xs[d] = xn;
    __syncthreads();
    float rot = (d < 64) ? -xs[d + 64] : xs[d - 64];
    float cs = ctab[(size_t)t * HD + d];
    float sn = stab[(size_t)t * HD + d];
    row[d] = xn * cs + rot * sn;
}

// ---------- flash attention (TF32 mma, online softmax) ----------
// Br=128 (8 warps x 16 rows), Bc=64, 256 threads, one block per (q-tile, head).
// Epilogue writes output pre-split into bf16 hi/lo (for the bf16-split O-proj).
constexpr int FLASH_SMEM_FLOATS = 128 * 132 + 64 * 132 + 64 * 136 + 128 * 68;
constexpr int FLASH_SMEM = FLASH_SMEM_FLOATS * 4;

__global__ __launch_bounds__(256, 1) void flash_attn(
    const float* __restrict__ Q, const float* __restrict__ Kp, const float* __restrict__ Vp,
    __nv_bfloat16* __restrict__ Ohi, __nv_bfloat16* __restrict__ Olo)
{
    extern __shared__ float sm[];
    float* Qs = sm;                       // [128][132]
    float* Ks = Qs + 128 * 132;           // [64][132]
    float* Vs = Ks + 64 * 132;            // [64][136]
    float* Ps = Vs + 64 * 136;            // [128][68]

    const int qi  = blockIdx.x;           // 0..31
    const int h   = blockIdx.y;           // 0..15
    const int kvh = h >> 2;
    const int tid = threadIdx.x;
    const int lane = tid & 31, wid = tid >> 5;
    const int g = lane >> 2, tg = lane & 3;
    const float qscale = 0.08838834764831845f; // 1/sqrt(128)

    #pragma unroll
    for (int p = 0; p < 16; p++) {
        int idx = (p << 10) + (tid << 2);
        int r = idx >> 7, c = idx & 127;
        float4 v = *reinterpret_cast<const float4*>(Q + (size_t)(qi * 128 + r) * CC + h * HD + c);
        float4 w = make_float4(tf2f(f2tf(v.x * qscale)), tf2f(f2tf(v.y * qscale)),
                               tf2f(f2tf(v.z * qscale)), tf2f(f2tf(v.w * qscale)));
        *reinterpret_cast<float4*>(&Qs[r * 132 + c]) = w;
    }

    const int wrow = wid << 4;
    const int grow = qi * 128 + wrow;
    float mst[2] = {-1e30f, -1e30f};
    float lst[2] = {0.f, 0.f};
    float oacc[16][4] = {};

    const int njt = 2 * qi + 2;
    for (int j = 0; j < njt; j++) {
        #pragma unroll
        for (int p = 0; p < 8; p++) {
            int idx = (p << 10) + (tid << 2);
            int r = idx >> 7, c = idx & 127;
            size_t goff = (size_t)(j * 64 + r) * (NKV * HD) + kvh * HD + c;
            float4 kv = *reinterpret_cast<const float4*>(Kp + goff);
            *reinterpret_cast<float4*>(&Ks[r * 132 + c]) =
                make_float4(tf2f(f2tf(kv.x)), tf2f(f2tf(kv.y)), tf2f(f2tf(kv.z)), tf2f(f2tf(kv.w)));
            float4 vv = *reinterpret_cast<const float4*>(Vp + goff);
            *reinterpret_cast<float4*>(&Vs[r * 136 + c]) =
                make_float4(tf2f(f2tf(vv.x)), tf2f(f2tf(vv.y)), tf2f(f2tf(vv.z)), tf2f(f2tf(vv.w)));
        }
        __syncthreads();

        const int jc0 = j << 6;
        if (jc0 <= grow + 15) {
            float sacc[8][4] = {};
            #pragma unroll
            for (int ks = 0; ks < 16; ks++) {
                const int kk = ks << 3;
                unsigned a[4];
                a[0] = __float_as_uint(Qs[(wrow + g) * 132 + kk + tg]);
                a[1] = __float_as_uint(Qs[(wrow + g + 8) * 132 + kk + tg]);
                a[2] = __float_as_uint(Qs[(wrow + g) * 132 + kk + tg + 4]);
                a[3] = __float_as_uint(Qs[(wrow + g + 8) * 132 + kk + tg + 4]);
                #pragma unroll
                for (int nt = 0; nt < 8; nt++) {
                    unsigned b[2];
                    b[0] = __float_as_uint(Ks[((nt << 3) + g) * 132 + kk + tg]);
                    b[1] = __float_as_uint(Ks[((nt << 3) + g) * 132 + kk + tg + 4]);
                    mma_tf32(sacc[nt], a, b);
                }
            }
            if (jc0 + 63 > grow) {
                #pragma unroll
                for (int nt = 0; nt < 8; nt++) {
                    int c0 = jc0 + (nt << 3) + (tg << 1);
                    int r0 = grow + g, r1 = r0 + 8;
                    if (c0     > r0) sacc[nt][0] = -1e30f;
                    if (c0 + 1 > r0) sacc[nt][1] = -1e30f;
                    if (c0     > r1) sacc[nt][2] = -1e30f;
                    if (c0 + 1 > r1) sacc[nt][3] = -1e30f;
                }
            }
            float rmax0 = -1e30f, rmax1 = -1e30f;
            #pragma unroll
            for (int nt = 0; nt < 8; nt++) {
                rmax0 = fmaxf(rmax0, fmaxf(sacc[nt][0], sacc[nt][1]));
                rmax1 = fmaxf(rmax1, fmaxf(sacc[nt][2], sacc[nt][3]));
            }
            rmax0 = fmaxf(rmax0, __shfl_xor_sync(0xffffffffu, rmax0, 1));
            rmax0 = fmaxf(rmax0, __shfl_xor_sync(0xffffffffu, rmax0, 2));
            rmax1 = fmaxf(rmax1, __shfl_xor_sync(0xffffffffu, rmax1, 1));
            rmax1 = fmaxf(rmax1, __shfl_xor_sync(0xffffffffu, rmax1, 2));
            float mnew0 = fmaxf(mst[0], rmax0);
            float mnew1 = fmaxf(mst[1], rmax1);
            float al0 = __expf(mst[0] - mnew0);
            float al1 = __expf(mst[1] - mnew1);
            mst[0] = mnew0; mst[1] = mnew1;

            float rs0 = 0.f, rs1 = 0.f;
            #pragma unroll
            for (int nt = 0; nt < 8; nt++) {
                float p0 = __expf(sacc[nt][0] - mnew0);
                float p1 = __expf(sacc[nt][1] - mnew0);
                float p2 = __expf(sacc[nt][2] - mnew1);
                float p3 = __expf(sacc[nt][3] - mnew1);
                rs0 += p0 + p1; rs1 += p2 + p3;
                int col = (nt << 3) + (tg << 1);
                *reinterpret_cast<float2*>(&Ps[(wrow + g) * 68 + col]) =
                    make_float2(tf2f(f2tf(p0)), tf2f(f2tf(p1)));
                *reinterpret_cast<float2*>(&Ps[(wrow + g + 8) * 68 + col]) =
                    make_float2(tf2f(f2tf(p2)), tf2f(f2tf(p3)));
            }
            rs0 += __shfl_xor_sync(0xffffffffu, rs0, 1);
            rs0 += __shfl_xor_sync(0xffffffffu, rs0, 2);
            rs1 += __shfl_xor_sync(0xffffffffu, rs1, 1);
            rs1 += __shfl_xor_sync(0xffffffffu, rs1, 2);
            lst[0] = lst[0] * al0 + rs0;
            lst[1] = lst[1] * al1 + rs1;
            #pragma unroll
            for (int nt = 0; nt < 16; nt++) {
                oacc[nt][0] *= al0; oacc[nt][1] *= al0;
                oacc[nt][2] *= al1; oacc[nt][3] *= al1;
            }
            __syncwarp();
            #pragma unroll
            for (int ks = 0; ks < 8; ks++) {
                const int kk = ks << 3;
                unsigned a[4];
                a[0] = __float_as_uint(Ps[(wrow + g) * 68 + kk + tg]);
                a[1] = __float_as_uint(Ps[(wrow + g + 8) * 68 + kk + tg]);
                a[2] = __float_as_uint(Ps[(wrow + g) * 68 + kk + tg + 4]);
                a[3] = __float_as_uint(Ps[(wrow + g + 8) * 68 + kk + tg + 4]);
                #pragma unroll
                for (int nt = 0; nt < 16; nt++) {
                    unsigned b[2];
                    b[0] = __float_as_uint(Vs[(kk + tg) * 136 + (nt << 3) + g]);
                    b[1] = __float_as_uint(Vs[(kk + tg + 4) * 136 + (nt << 3) + g]);
                    mma_tf32(oacc[nt], a, b);
                }
            }
        }
        __syncthreads();
    }

    float li0 = 1.0f / lst[0];
    float li1 = 1.0f / lst[1];
    #pragma unroll
    for (int nt = 0; nt < 16; nt++) {
        int col = h * HD + (nt << 3) + (tg << 1);
        float v0 = oacc[nt][0] * li0, v1 = oacc[nt][1] * li0;
        float v2 = oacc[nt][2] * li1, v3 = oacc[nt][3] * li1;
        __nv_bfloat16 h0, h1, h2, h3, l0, l1, l2, l3;
        bsplit(v0, h0, l0); bsplit(v1, h1, l1);
        bsplit(v2, h2, l2); bsplit(v3, h3, l3);
        size_t o0 = ((size_t)(grow + g) * CC + col) >> 1;
        size_t o1 = ((size_t)(grow + g + 8) * CC + col) >> 1;
        __nv_bfloat162 ph0; ph0.x = h0; ph0.y = h1;
        __nv_bfloat162 ph1; ph1.x = h2; ph1.y = h3;
        __nv_bfloat162 pl0; pl0.x = l0; pl0.y = l1;
        __nv_bfloat162 pl1; pl1.x = l2; pl1.y = l3;
        reinterpret_cast<__nv_bfloat162*>(Ohi)[o0] = ph0;
        reinterpret_cast<__nv_bfloat162*>(Ohi)[o1] = ph1;
        reinterpret_cast<__nv_bfloat162*>(Olo)[o0] = pl0;
        reinterpret_cast<__nv_bfloat162*>(Olo)[o1] = pl1;
    }
}

// ---------- launch ----------
extern "C" void kernel_launch(void* const* d_in, const int* in_sizes, int n_in,
                              void* d_out, int out_size)
{
    const float* x  = (const float*)d_in[0];
    const float* Wq = (const float*)d_in[1];
    const float* Wk = (const float*)d_in[2];
    const float* Wv = (const float*)d_in[3];
    const float* Wo = (const float*)d_in[4];
    float* out = (float*)d_out;

    float *pq, *pk, *pv, *pc, *ps;
    __nv_bfloat16 *pahi, *palo, *pxhi, *pxlo;
    uint32_t *pwqh, *pwql, *pwkh, *pwkl, *pwvh, *pwvl, *pwoh, *pwol;
    cudaGetSymbolAddress((void**)&pq, g_q);
    cudaGetSymbolAddress((void**)&pk, g_k);
    cudaGetSymbolAddress((void**)&pv, g_v);
    cudaGetSymbolAddress((void**)&pahi, g_atthi);
    cudaGetSymbolAddress((void**)&palo, g_attlo);
    cudaGetSymbolAddress((void**)&pc, g_cos);
    cudaGetSymbolAddress((void**)&ps, g_sin);
    cudaGetSymbolAddress((void**)&pxhi, g_xhi);
    cudaGetSymbolAddress((void**)&pxlo, g_xlo);
    cudaGetSymbolAddress((void**)&pwqh, g_wqhi);
    cudaGetSymbolAddress((void**)&pwql, g_wqlo);
    cudaGetSymbolAddress((void**)&pwkh, g_wkhi);
    cudaGetSymbolAddress((void**)&pwkl, g_wklo);
    cudaGetSymbolAddress((void**)&pwvh, g_wvhi);
    cudaGetSymbolAddress((void**)&pwvl, g_wvlo);
    cudaGetSymbolAddress((void**)&pwoh, g_wohi);
    cudaGetSymbolAddress((void**)&pwol, g_wolo);

    cudaFuncSetAttribute(gemm_bf16s, cudaFuncAttributeMaxDynamicSharedMemorySize, GEMM_SMEM);
    cudaFuncSetAttribute(flash_attn, cudaFuncAttributeMaxDynamicSharedMemorySize, FLASH_SMEM);

    // pre-split operands (launch order keeps the Q-proj GEMM at ncu -s 5)
    split_a<<<(TT * CC) / 1024, 256>>>(x, pxhi, pxlo);
    split_b<<<dim3(CC / 256, CC / 2), 256>>>(Wq, pwqh, pwql, CC);
    split_b<<<dim3((NKV * HD) / 256, CC / 2), 256>>>(Wk, pwkh, pwkl, NKV * HD);
    split_b<<<dim3((NKV * HD) / 256, CC / 2), 256>>>(Wv, pwvh, pwvl, NKV * HD);
    split_b<<<dim3(CC / 256, CC / 2), 256>>>(Wo, pwoh, pwol, CC);

    // Q projection: 16 n-tiles x 32 m-tiles
    gemm_bf16s<<<dim3(16, 32), 256, GEMM_SMEM>>>(
        (const uint32_t*)pxhi, (const uint32_t*)pxlo,
        pwqh, pwql, pwqh, pwql, pq, pq, CC, 16, CC, CC);
    // K and V projections fused: 4 + 4 n-tiles
    gemm_bf16s<<<dim3(8, 32), 256, GEMM_SMEM>>>(
        (const uint32_t*)pxhi, (const uint32_t*)pxlo,
        pwkh, pwkl, pwvh, pwvl, pk, pv, CC, 4, NKV * HD, NKV * HD);

    rope_table_kernel<<<TT, 128>>>(pc, ps);
    rmsnorm_rope<<<dim3(TT, NH), 128>>>(pq, pc, ps, NH);
    rmsnorm_rope<<<dim3(TT, NKV), 128>>>(pk, pc, ps, NKV);

    flash_attn<<<dim3(TT / 128, NH), 256, FLASH_SMEM>>>(pq, pk, pv, pahi, palo);

    // output projection
    gemm_bf16s<<<dim3(16, 32), 256, GEMM_SMEM>>>(
        (const uint32_t*)pahi, (const uint32_t*)palo,
        pwoh, pwol, pwoh, pwol, out, out, CC, 16, CC, CC);
}

// round 15
// speedup vs baseline: 1.0016x; 1.0016x over previous
#include <cuda_runtime.h>
#include <cuda_bf16.h>
#include <math.h>
#include <stdint.h>

// Problem constants
constexpr int TT  = 4096;   // sequence length
constexpr int CC  = 2048;   // model dim
constexpr int NH  = 16;     // query heads
constexpr int NKV = 4;      // kv heads
constexpr int HD  = 128;    // head dim

// Scratch (device globals; no allocation allowed)
__device__ float g_q[(size_t)TT * CC];
__device__ float g_k[(size_t)TT * NKV * HD];
__device__ float g_v[(size_t)TT * NKV * HD];
__device__ __nv_bfloat16 g_atthi[(size_t)TT * CC];
__device__ __nv_bfloat16 g_attlo[(size_t)TT * CC];
__device__ __nv_bfloat16 g_xhi[(size_t)TT * CC];
__device__ __nv_bfloat16 g_xlo[(size_t)TT * CC];
// weights pair-packed: [K/2][N] uint32, each uint32 = (bf16 k=2kp, bf16 k=2kp+1)
__device__ uint32_t g_wqhi[(size_t)(CC / 2) * CC];
__device__ uint32_t g_wqlo[(size_t)(CC / 2) * CC];
__device__ uint32_t g_wkhi[(size_t)(CC / 2) * NKV * HD];
__device__ uint32_t g_wklo[(size_t)(CC / 2) * NKV * HD];
__device__ uint32_t g_wvhi[(size_t)(CC / 2) * NKV * HD];
__device__ uint32_t g_wvlo[(size_t)(CC / 2) * NKV * HD];
__device__ uint32_t g_wohi[(size_t)(CC / 2) * CC];
__device__ uint32_t g_wolo[(size_t)(CC / 2) * CC];
__device__ float g_cos[(size_t)TT * HD];
__device__ float g_sin[(size_t)TT * HD];

// ---------- helpers ----------
__device__ __forceinline__ unsigned f2tf(float x) {
    unsigned u; asm("cvt.rna.tf32.f32 %0, %1;" : "=r"(u) : "f"(x)); return u;
}
__device__ __forceinline__ float tf2f(unsigned u) { return __uint_as_float(u); }

__device__ __forceinline__ void mma_tf32(float c[4], const unsigned a[4], const unsigned b[2]) {
    asm volatile(
        "mma.sync.aligned.m16n8k8.row.col.f32.tf32.tf32.f32 "
        "{%0,%1,%2,%3}, {%4,%5,%6,%7}, {%8,%9}, {%0,%1,%2,%3};\n"
        : "+f"(c[0]), "+f"(c[1]), "+f"(c[2]), "+f"(c[3])
        : "r"(a[0]), "r"(a[1]), "r"(a[2]), "r"(a[3]), "r"(b[0]), "r"(b[1]));
}

__device__ __forceinline__ void mma_bf16(float c[4], const unsigned a[4], const unsigned b[2]) {
    asm volatile(
        "mma.sync.aligned.m16n8k16.row.col.f32.bf16.bf16.f32 "
        "{%0,%1,%2,%3}, {%4,%5,%6,%7}, {%8,%9}, {%0,%1,%2,%3};\n"
        : "+f"(c[0]), "+f"(c[1]), "+f"(c[2]), "+f"(c[3])
        : "r"(a[0]), "r"(a[1]), "r"(a[2]), "r"(a[3]), "r"(b[0]), "r"(b[1]));
}

__device__ __forceinline__ uint32_t cvta_smem(const void* p) {
    uint32_t a;
    asm("{ .reg .u64 t; cvta.to.shared.u64 t, %1; cvt.u32.u64 %0, t; }" : "=r"(a) : "l"(p));
    return a;
}
__device__ __forceinline__ void cpa16(uint32_t dst, const void* src) {
    asm volatile("cp.async.cg.shared.global [%0], [%1], 16;" :: "r"(dst), "l"(src) : "memory");
}
__device__ __forceinline__ void cpa_commit() {
    asm volatile("cp.async.commit_group;" ::: "memory");
}
template<int N> __device__ __forceinline__ void cpa_wait() {
    asm volatile("cp.async.wait_group %0;" :: "n"(N) : "memory");
}

__device__ __forceinline__ void bsplit(float v, __nv_bfloat16 &h, __nv_bfloat16 &l) {
    h = __float2bfloat16_rn(v);
    l = __float2bfloat16_rn(v - __bfloat162float(h));
}

// ---------- RoPE tables (fp64-accurate) ----------
__global__ void rope_table_kernel(float* __restrict__ ctab, float* __restrict__ stab) {
    int t = blockIdx.x;
    int d = threadIdx.x;            // 0..127
    int fi = d & 63;
    double inv = exp(-(double)fi * (log(10000.0) / 64.0));
    double ang = (double)t * inv;
    ctab[(size_t)t * HD + d] = (float)cos(ang);
    stab[(size_t)t * HD + d] = (float)sin(ang);
}

// ---------- A-side split: fp32 row-major -> bf16 hi/lo row-major ----------
__global__ __launch_bounds__(256) void split_a(
    const float* __restrict__ in, __nv_bfloat16* __restrict__ hi, __nv_bfloat16* __restrict__ lo)
{
    size_t i = (size_t)blockIdx.x * 256 + threadIdx.x;      // over elems/4
    float4 v = reinterpret_cast<const float4*>(in)[i];
    __nv_bfloat16 h0, h1, h2, h3, l0, l1, l2, l3;
    bsplit(v.x, h0, l0); bsplit(v.y, h1, l1); bsplit(v.z, h2, l2); bsplit(v.w, h3, l3);
    __nv_bfloat162 ph0; ph0.x = h0; ph0.y = h1;
    __nv_bfloat162 ph1; ph1.x = h2; ph1.y = h3;
    __nv_bfloat162 pl0; pl0.x = l0; pl0.y = l1;
    __nv_bfloat162 pl1; pl1.x = l2; pl1.y = l3;
    reinterpret_cast<__nv_bfloat162*>(hi)[2 * i]     = ph0;
    reinterpret_cast<__nv_bfloat162*>(hi)[2 * i + 1] = ph1;
    reinterpret_cast<__nv_bfloat162*>(lo)[2 * i]     = pl0;
    reinterpret_cast<__nv_bfloat162*>(lo)[2 * i + 1] = pl1;
}

// ---------- B-side split + k-pair pack: fp32 [K][N] -> uint32 [K/2][N] ----------
__global__ __launch_bounds__(256) void split_b(
    const float* __restrict__ B, uint32_t* __restrict__ hi, uint32_t* __restrict__ lo, int N)
{
    int n  = blockIdx.x * 256 + threadIdx.x;
    int kp = blockIdx.y;
    float v0 = B[(size_t)(2 * kp) * N + n];
    float v1 = B[(size_t)(2 * kp + 1) * N + n];
    __nv_bfloat16 h0, h1, l0, l1;
    bsplit(v0, h0, l0);
    bsplit(v1, h1, l1);
    __nv_bfloat162 ph; ph.x = h0; ph.y = h1;
    __nv_bfloat162 pl; pl.x = l0; pl.y = l1;
    hi[(size_t)kp * N + n] = *reinterpret_cast<uint32_t*>(&ph);
    lo[(size_t)kp * N + n] = *reinterpret_cast<uint32_t*>(&pl);
}

// ---------- split-bf16 GEMM (3-term, pair-packed, cp.async double-buffered) ----------
// C[M,N] = A[M,K] @ B[K,N]; A as hi/lo bf16 row-major (uint32 pairs along K),
// B as hi/lo pair-packed [K/2][N] uint32. 128x128 tile, BK=32 (16 pairs),
// 256 threads (8 warps as 4m x 2n), warp tile 32x64, m16n8k16 bf16 mma.
constexpr int BKP   = 16;                 // k-pairs per tile (= 32 k)
constexpr int A_LD  = 20;                 // uint32 lead (16 used + 4 pad)
constexpr int B_LD  = 136;                // uint32 lead (128 used + 8 pad)
constexpr int SZ_A  = 128 * A_LD;         // 2560 uint32 per A buffer
constexpr int SZ_B  = BKP * B_LD;         // 2176 uint32 per B buffer
constexpr int STGU  = 2 * SZ_A + 2 * SZ_B;   // 9472 uint32 per stage
constexpr int GEMM_SMEM = 2 * STGU * 4;      // 75776 bytes

__global__ __launch_bounds__(256, 2) void gemm_bf16s(
    const uint32_t* __restrict__ Ahi, const uint32_t* __restrict__ Alo,
    const uint32_t* __restrict__ Bh0, const uint32_t* __restrict__ Bl0,
    const uint32_t* __restrict__ Bh1, const uint32_t* __restrict__ Bl1,
    float* __restrict__ C0, float* __restrict__ C1,
    int Kdim, int n0tiles, int Nc0, int Nc1)
{
    extern __shared__ uint32_t smu[];
    const uint32_t sb = cvta_smem(smu);
    const int tid  = threadIdx.x;
    const int lane = tid & 31;
    const int wid  = tid >> 5;
    const int g    = lane >> 2;     // 0..7
    const int tg   = lane & 3;      // 0..3
    const int wm   = (wid & 3) << 5;    // 0,32,64,96
    const int wn   = (wid >> 2) << 6;   // 0,64
    const int bm   = blockIdx.y << 7;
    const int KP   = Kdim >> 1;

    const uint32_t *Bhi, *Blo; float* C; int Nc, bn;
    if ((int)blockIdx.x < n0tiles) { Bhi = Bh0; Blo = Bl0; C = C0; Nc = Nc0; bn = blockIdx.x << 7; }
    else                           { Bhi = Bh1; Blo = Bl1; C = C1; Nc = Nc1; bn = (blockIdx.x - n0tiles) << 7; }

    // copy coordinates
    const int arow = tid >> 1;            // 0..127
    const int acnk = (tid & 1) << 1;      // chunk base 0 or 2 (chunks of 4 uint32)
    const int brow = tid >> 4;            // 0..15
    const int bcnk = tid & 15;            // 0..15 (+16)

    const uint32_t* Asrc_h = Ahi + (size_t)(bm + arow) * KP + (acnk << 2);
    const uint32_t* Asrc_l = Alo + (size_t)(bm + arow) * KP + (acnk << 2);
    const uint32_t* Bsrc_h = Bhi + (size_t)brow * Nc + bn + (bcnk << 2);
    const uint32_t* Bsrc_l = Blo + (size_t)brow * Nc + bn + (bcnk << 2);

    auto load_stage = [&](int s, int kp0) {
        const uint32_t st = sb + (uint32_t)(s * STGU) * 4;
        #pragma unroll
        for (int i = 0; i < 2; i++) {
            uint32_t d = st + (uint32_t)(arow * A_LD + ((acnk + i) << 2)) * 4;
            cpa16(d, Asrc_h + kp0 + (i << 2));
            cpa16(d + SZ_A * 4, Asrc_l + kp0 + (i << 2));
        }
        #pragma unroll
        for (int i = 0; i < 2; i++) {
            int c = bcnk + (i << 4);
            uint32_t d = st + (uint32_t)(2 * SZ_A + brow * B_LD + (c << 2)) * 4;
            cpa16(d, Bsrc_h + (size_t)kp0 * Nc + (i << 6));
            cpa16(d + SZ_B * 4, Bsrc_l + (size_t)kp0 * Nc + (i << 6));
        }
        cpa_commit();
    };

    float acc[2][8][4];
    #pragma unroll
    for (int i = 0; i < 2; i++)
        #pragma unroll
        for (int j = 0; j < 8; j++)
            #pragma unroll
            for (int q = 0; q < 4; q++) acc[i][j][q] = 0.f;

    const int nkt = Kdim >> 5;
    load_stage(0, 0);

    for (int kt = 0; kt < nkt; kt++) {
        if (kt + 1 < nkt) { load_stage((kt + 1) & 1, (kt + 1) * BKP); cpa_wait<1>(); }
        else             { cpa_wait<0>(); }
        __syncthreads();

        const uint32_t* buf = smu + (kt & 1) * STGU;
        const uint32_t* Ah = buf;
        const uint32_t* Al = buf + SZ_A;
        const uint32_t* Bh = buf + 2 * SZ_A;
        const uint32_t* Bl = buf + 2 * SZ_A + SZ_B;

        #pragma unroll
        for (int ks = 0; ks < 2; ks++) {
            const int kpq = (ks << 3) + tg;
            unsigned ahi[2][4], alo[2][4];
            #pragma unroll
            for (int mt = 0; mt < 2; mt++) {
                const int mr = wm + (mt << 4) + g;
                ahi[mt][0] = Ah[mr * A_LD + kpq];
                ahi[mt][1] = Ah[(mr + 8) * A_LD + kpq];
                ahi[mt][2] = Ah[mr * A_LD + kpq + 4];
                ahi[mt][3] = Ah[(mr + 8) * A_LD + kpq + 4];
                alo[mt][0] = Al[mr * A_LD + kpq];
                alo[mt][1] = Al[(mr + 8) * A_LD + kpq];
                alo[mt][2] = Al[mr * A_LD + kpq + 4];
                alo[mt][3] = Al[(mr + 8) * A_LD + kpq + 4];
            }
            #pragma unroll
            for (int nt = 0; nt < 8; nt++) {
                const int nc = wn + (nt << 3) + g;
                unsigned bh[2], bl[2];
                bh[0] = Bh[kpq * B_LD + nc];
                bh[1] = Bh[(kpq + 4) * B_LD + nc];
                bl[0] = Bl[kpq * B_LD + nc];
                bl[1] = Bl[(kpq + 4) * B_LD + nc];
                #pragma unroll
                for (int mt = 0; mt < 2; mt++) {
                    mma_bf16(acc[mt][nt], ahi[mt], bh);
                    mma_bf16(acc[mt][nt], alo[mt], bh);
                    mma_bf16(acc[mt][nt], ahi[mt], bl);
                }
            }
        }
        __syncthreads();
    }

    #pragma unroll
    for (int mt = 0; mt < 2; mt++) {
        #pragma unroll
        for (int nt = 0; nt < 8; nt++) {
            const int row0 = bm + wm + (mt << 4) + g;
            const int col  = bn + wn + (nt << 3) + (tg << 1);
            *reinterpret_cast<float2*>(C + (size_t)row0 * Nc + col) =
                make_float2(acc[mt][nt][0], acc[mt][nt][1]);
            *reinterpret_cast<float2*>(C + (size_t)(row0 + 8) * Nc + col) =
                make_float2(acc[mt][nt][2], acc[mt][nt][3]);
        }
    }
}

// ---------- fused RMSnorm + RoPE (per (t, head) row of 128) ----------
__global__ __launch_bounds__(128) void rmsnorm_rope(
    float* __restrict__ p, const float* __restrict__ ctab, const float* __restrict__ stab, int nh)
{
    const int t = blockIdx.x;
    const int h = blockIdx.y;
    const int d = threadIdx.x;      // 0..127
    const int stride = nh * HD;
    float* row = p + (size_t)t * stride + h * HD;

    float v = row[d];
    float s = v * v;
    #pragma unroll
    for (int o = 16; o > 0; o >>= 1) s += __shfl_xor_sync(0xffffffffu, s, o);
    __shared__ float ws[4];
    __shared__ float xs[128];
    if ((d & 31) == 0) ws[d >> 5] = s;
    __syncthreads();
    float tot = ws[0] + ws[1] + ws[2] + ws[3];
    float r = rsqrtf(tot * (1.0f / 128.0f) + 1e-6f);
    float xn = v * r;
    xs[d] = xn;
    __syncthreads();
    float rot = (d < 64) ? -xs[d + 64] : xs[d - 64];
    float cs = ctab[(size_t)t * HD + d];
    float sn = stab[(size_t)t * HD + d];
    row[d] = xn * cs + rot * sn;
}

// ---------- flash attention (TF32 mma, online softmax) ----------
// Br=128 (8 warps x 16 rows), Bc=64, 256 threads, one block per (q-tile, head).
// Epilogue writes output pre-split into bf16 hi/lo (for the bf16-split O-proj).
constexpr int FLASH_SMEM_FLOATS = 128 * 132 + 64 * 132 + 64 * 136 + 128 * 68;
constexpr int FLASH_SMEM = FLASH_SMEM_FLOATS * 4;

__global__ __launch_bounds__(256, 1) void flash_attn(
    const float* __restrict__ Q, const float* __restrict__ Kp, const float* __restrict__ Vp,
    __nv_bfloat16* __restrict__ Ohi, __nv_bfloat16* __restrict__ Olo)
{
    extern __shared__ float sm[];
    float* Qs = sm;                       // [128][132]
    float* Ks = Qs + 128 * 132;           // [64][132]
    float* Vs = Ks + 64 * 132;            // [64][136]
    float* Ps = Vs + 64 * 136;            // [128][68]

    const int qi  = blockIdx.x;           // 0..31
    const int h   = blockIdx.y;           // 0..15
    const int kvh = h >> 2;
    const int tid = threadIdx.x;
    const int lane = tid & 31, wid = tid >> 5;
    const int g = lane >> 2, tg = lane & 3;
    const float qscale = 0.08838834764831845f; // 1/sqrt(128)

    #pragma unroll
    for (int p = 0; p < 16; p++) {
        int idx = (p << 10) + (tid << 2);
        int r = idx >> 7, c = idx & 127;
        float4 v = *reinterpret_cast<const float4*>(Q + (size_t)(qi * 128 + r) * CC + h * HD + c);
        float4 w = make_float4(tf2f(f2tf(v.x * qscale)), tf2f(f2tf(v.y * qscale)),
                               tf2f(f2tf(v.z * qscale)), tf2f(f2tf(v.w * qscale)));
        *reinterpret_cast<float4*>(&Qs[r * 132 + c]) = w;
    }

    const int wrow = wid << 4;
    const int grow = qi * 128 + wrow;
    float mst[2] = {-1e30f, -1e30f};
    float lst[2] = {0.f, 0.f};
    float oacc[16][4] = {};

    const int njt = 2 * qi + 2;
    for (int j = 0; j < njt; j++) {
        #pragma unroll
        for (int p = 0; p < 8; p++) {
            int idx = (p << 10) + (tid << 2);
            int r = idx >> 7, c = idx & 127;
            size_t goff = (size_t)(j * 64 + r) * (NKV * HD) + kvh * HD + c;
            float4 kv = *reinterpret_cast<const float4*>(Kp + goff);
            *reinterpret_cast<float4*>(&Ks[r * 132 + c]) =
                make_float4(tf2f(f2tf(kv.x)), tf2f(f2tf(kv.y)), tf2f(f2tf(kv.z)), tf2f(f2tf(kv.w)));
            float4 vv = *reinterpret_cast<const float4*>(Vp + goff);
            *reinterpret_cast<float4*>(&Vs[r * 136 + c]) =
                make_float4(tf2f(f2tf(vv.x)), tf2f(f2tf(vv.y)), tf2f(f2tf(vv.z)), tf2f(f2tf(vv.w)));
        }
        __syncthreads();

        const int jc0 = j << 6;
        if (jc0 <= grow + 15) {
            float sacc[8][4] = {};
            #pragma unroll
            for (int ks = 0; ks < 16; ks++) {
                const int kk = ks << 3;
                unsigned a[4];
                a[0] = __float_as_uint(Qs[(wrow + g) * 132 + kk + tg]);
                a[1] = __float_as_uint(Qs[(wrow + g + 8) * 132 + kk + tg]);
                a[2] = __float_as_uint(Qs[(wrow + g) * 132 + kk + tg + 4]);
                a[3] = __float_as_uint(Qs[(wrow + g + 8) * 132 + kk + tg + 4]);
                #pragma unroll
                for (int nt = 0; nt < 8; nt++) {
                    unsigned b[2];
                    b[0] = __float_as_uint(Ks[((nt << 3) + g) * 132 + kk + tg]);
                    b[1] = __float_as_uint(Ks[((nt << 3) + g) * 132 + kk + tg + 4]);
                    mma_tf32(sacc[nt], a, b);
                }
            }
            if (jc0 + 63 > grow) {
                #pragma unroll
                for (int nt = 0; nt < 8; nt++) {
                    int c0 = jc0 + (nt << 3) + (tg << 1);
                    int r0 = grow + g, r1 = r0 + 8;
                    if (c0     > r0) sacc[nt][0] = -1e30f;
                    if (c0 + 1 > r0) sacc[nt][1] = -1e30f;
                    if (c0     > r1) sacc[nt][2] = -1e30f;
                    if (c0 + 1 > r1) sacc[nt][3] = -1e30f;
                }
            }
            float rmax0 = -1e30f, rmax1 = -1e30f;
            #pragma unroll
            for (int nt = 0; nt < 8; nt++) {
                rmax0 = fmaxf(rmax0, fmaxf(sacc[nt][0], sacc[nt][1]));
                rmax1 = fmaxf(rmax1, fmaxf(sacc[nt][2], sacc[nt][3]));
            }
            rmax0 = fmaxf(rmax0, __shfl_xor_sync(0xffffffffu, rmax0, 1));
            rmax0 = fmaxf(rmax0, __shfl_xor_sync(0xffffffffu, rmax0, 2));
            rmax1 = fmaxf(rmax1, __shfl_xor_sync(0xffffffffu, rmax1, 1));
            rmax1 = fmaxf(rmax1, __shfl_xor_sync(0xffffffffu, rmax1, 2));
            float mnew0 = fmaxf(mst[0], rmax0);
            float mnew1 = fmaxf(mst[1], rmax1);
            float al0 = __expf(mst[0] - mnew0);
            float al1 = __expf(mst[1] - mnew1);
            mst[0] = mnew0; mst[1] = mnew1;

            float rs0 = 0.f, rs1 = 0.f;
            #pragma unroll
            for (int nt = 0; nt < 8; nt++) {
                float p0 = __expf(sacc[nt][0] - mnew0);
                float p1 = __expf(sacc[nt][1] - mnew0);
                float p2 = __expf(sacc[nt][2] - mnew1);
                float p3 = __expf(sacc[nt][3] - mnew1);
                rs0 += p0 + p1; rs1 += p2 + p3;
                int col = (nt << 3) + (tg << 1);
                *reinterpret_cast<float2*>(&Ps[(wrow + g) * 68 + col]) =
                    make_float2(tf2f(f2tf(p0)), tf2f(f2tf(p1)));
                *reinterpret_cast<float2*>(&Ps[(wrow + g + 8) * 68 + col]) =
                    make_float2(tf2f(f2tf(p2)), tf2f(f2tf(p3)));
            }
            rs0 += __shfl_xor_sync(0xffffffffu, rs0, 1);
            rs0 += __shfl_xor_sync(0xffffffffu, rs0, 2);
            rs1 += __shfl_xor_sync(0xffffffffu, rs1, 1);
            rs1 += __shfl_xor_sync(0xffffffffu, rs1, 2);
            lst[0] = lst[0] * al0 + rs0;
            lst[1] = lst[1] * al1 + rs1;
            #pragma unroll
            for (int nt = 0; nt < 16; nt++) {
                oacc[nt][0] *= al0; oacc[nt][1] *= al0;
                oacc[nt][2] *= al1; oacc[nt][3] *= al1;
            }
            __syncwarp();
            #pragma unroll
            for (int ks = 0; ks < 8; ks++) {
                const int kk = ks << 3;
                unsigned a[4];
                a[0] = __float_as_uint(Ps[(wrow + g) * 68 + kk + tg]);
                a[1] = __float_as_uint(Ps[(wrow + g + 8) * 68 + kk + tg]);
                a[2] = __float_as_uint(Ps[(wrow + g) * 68 + kk + tg + 4]);
                a[3] = __float_as_uint(Ps[(wrow + g + 8) * 68 + kk + tg + 4]);
                #pragma unroll
                for (int nt = 0; nt < 16; nt++) {
                    unsigned b[2];
                    b[0] = __float_as_uint(Vs[(kk + tg) * 136 + (nt << 3) + g]);
                    b[1] = __float_as_uint(Vs[(kk + tg + 4) * 136 + (nt << 3) + g]);
                    mma_tf32(oacc[nt], a, b);
                }
            }
        }
        __syncthreads();
    }

    float li0 = 1.0f / lst[0];
    float li1 = 1.0f / lst[1];
    #pragma unroll
    for (int nt = 0; nt < 16; nt++) {
        int col = h * HD + (nt << 3) + (tg << 1);
        float v0 = oacc[nt][0] * li0, v1 = oacc[nt][1] * li0;
        float v2 = oacc[nt][2] * li1, v3 = oacc[nt][3] * li1;
        __nv_bfloat16 h0, h1, h2, h3, l0, l1, l2, l3;
        bsplit(v0, h0, l0); bsplit(v1, h1, l1);
        bsplit(v2, h2, l2); bsplit(v3, h3, l3);
        size_t o0 = ((size_t)(grow + g) * CC + col) >> 1;
        size_t o1 = ((size_t)(grow + g + 8) * CC + col) >> 1;
        __nv_bfloat162 ph0; ph0.x = h0; ph0.y = h1;
        __nv_bfloat162 ph1; ph1.x = h2; ph1.y = h3;
        __nv_bfloat162 pl0; pl0.x = l0; pl0.y = l1;
        __nv_bfloat162 pl1; pl1.x = l2; pl1.y = l3;
        reinterpret_cast<__nv_bfloat162*>(Ohi)[o0] = ph0;
        reinterpret_cast<__nv_bfloat162*>(Ohi)[o1] = ph1;
        reinterpret_cast<__nv_bfloat162*>(Olo)[o0] = pl0;
        reinterpret_cast<__nv_bfloat162*>(Olo)[o1] = pl1;
    }
}

// ---------- launch ----------
extern "C" void kernel_launch(void* const* d_in, const int* in_sizes, int n_in,
                              void* d_out, int out_size)
{
    const float* x  = (const float*)d_in[0];
    const float* Wq = (const float*)d_in[1];
    const float* Wk = (const float*)d_in[2];
    const float* Wv = (const float*)d_in[3];
    const float* Wo = (const float*)d_in[4];
    float* out = (float*)d_out;

    float *pq, *pk, *pv, *pc, *ps;
    __nv_bfloat16 *pahi, *palo, *pxhi, *pxlo;
    uint32_t *pwqh, *pwql, *pwkh, *pwkl, *pwvh, *pwvl, *pwoh, *pwol;
    cudaGetSymbolAddress((void**)&pq, g_q);
    cudaGetSymbolAddress((void**)&pk, g_k);
    cudaGetSymbolAddress((void**)&pv, g_v);
    cudaGetSymbolAddress((void**)&pahi, g_atthi);
    cudaGetSymbolAddress((void**)&palo, g_attlo);
    cudaGetSymbolAddress((void**)&pc, g_cos);
    cudaGetSymbolAddress((void**)&ps, g_sin);
    cudaGetSymbolAddress((void**)&pxhi, g_xhi);
    cudaGetSymbolAddress((void**)&pxlo, g_xlo);
    cudaGetSymbolAddress((void**)&pwqh, g_wqhi);
    cudaGetSymbolAddress((void**)&pwql, g_wqlo);
    cudaGetSymbolAddress((void**)&pwkh, g_wkhi);
    cudaGetSymbolAddress((void**)&pwkl, g_wklo);
    cudaGetSymbolAddress((void**)&pwvh, g_wvhi);
    cudaGetSymbolAddress((void**)&pwvl, g_wvlo);
    cudaGetSymbolAddress((void**)&pwoh, g_wohi);
    cudaGetSymbolAddress((void**)&pwol, g_wolo);

    cudaFuncSetAttribute(gemm_bf16s, cudaFuncAttributeMaxDynamicSharedMemorySize, GEMM_SMEM);
    cudaFuncSetAttribute(flash_attn, cudaFuncAttributeMaxDynamicSharedMemorySize, FLASH_SMEM);

    // pre-split operands (launch order keeps the Q-proj GEMM at ncu -s 5)
    split_a<<<(TT * CC) / 1024, 256>>>(x, pxhi, pxlo);
    split_b<<<dim3(CC / 256, CC / 2), 256>>>(Wq, pwqh, pwql, CC);
    split_b<<<dim3((NKV * HD) / 256, CC / 2), 256>>>(Wk, pwkh, pwkl, NKV * HD);
    split_b<<<dim3((NKV * HD) / 256, CC / 2), 256>>>(Wv, pwvh, pwvl, NKV * HD);
    split_b<<<dim3(CC / 256, CC / 2), 256>>>(Wo, pwoh, pwol, CC);

    // Q projection: 16 n-tiles x 32 m-tiles
    gemm_bf16s<<<dim3(16, 32), 256, GEMM_SMEM>>>(
        (const uint32_t*)pxhi, (const uint32_t*)pxlo,
        pwqh, pwql, pwqh, pwql, pq, pq, CC, 16, CC, CC);
    // K and V projections fused: 4 + 4 n-tiles
    gemm_bf16s<<<dim3(8, 32), 256, GEMM_SMEM>>>(
        (const uint32_t*)pxhi, (const uint32_t*)pxlo,
        pwkh, pwkl, pwvh, pwvl, pk, pv, CC, 4, NKV * HD, NKV * HD);

    rope_table_kernel<<<TT, 128>>>(pc, ps);
    rmsnorm_rope<<<dim3(TT, NH), 128>>>(pq, pc, ps, NH);
    rmsnorm_rope<<<dim3(TT, NKV), 128>>>(pk, pc, ps, NKV);

    flash_attn<<<dim3(TT / 128, NH), 256, FLASH_SMEM>>>(pq, pk, pv, pahi, palo);

    // output projection
    gemm_bf16s<<<dim3(16, 32), 256, GEMM_SMEM>>>(
        (const uint32_t*)pahi, (const uint32_t*)palo,
        pwoh, pwol, pwoh, pwol, out, out, CC, 16, CC, CC);
}